// round 1
// baseline (speedup 1.0000x reference)
#include <cuda_runtime.h>
#include <cstdint>

typedef unsigned long long ull;

#define MAXN (1 << 21)

__device__ ull   g_nodes[MAXN + 1];
__device__ float g_val[MAXN];

__device__ __forceinline__ ull pack_node(int p, float t) {
    return ((ull)__float_as_uint(t) << 32) | (unsigned int)(unsigned)p;
}

__global__ __launch_bounds__(256)
void phase1_kernel(const float* __restrict__ diff,
                   const float* __restrict__ attr,
                   const float* __restrict__ weight,
                   const float* __restrict__ bias,
                   const int*   __restrict__ parent,
                   int N)
{
    __shared__ float s_attr[256 * 15];
    const int base = blockIdx.x * 256;
    const int tid  = threadIdx.x;

    if (base + 256 <= N) {
        const float4* src = (const float4*)(attr + (size_t)base * 15);
        float4* dst = (float4*)s_attr;
        // 256*15 floats = 960 float4s per block
        dst[tid]       = src[tid];
        dst[tid + 256] = src[tid + 256];
        dst[tid + 512] = src[tid + 512];
        if (tid < 192) dst[tid + 768] = src[tid + 768];
    } else {
        const int rem = (N - base) * 15;
        for (int k = tid; k < rem; k += 256)
            s_attr[k] = attr[(size_t)base * 15 + k];
    }
    __syncthreads();

    const int i = base + tid;
    if (i >= N) return;

    const float* f = s_attr + tid * 15;

    float w[17];
    #pragma unroll
    for (int k = 0; k < 17; k++) w[k] = __ldg(weight + k);

    float z = __ldg(bias);
    z += w[0] * f[0] + w[1] * f[1] + w[2] * f[2] + w[3] * f[3] + w[4] * f[4];
    #pragma unroll
    for (int j = 6; j < 15; j++)
        z += w[j - 1] * __logf(fabsf(f[j]) + 1e-10f);
    z += w[14] * (sqrtf(f[7]) / (sqrtf(f[6]) + 1e-10f));
    float sn, cs;
    __sincosf(f[5], &sn, &cs);
    z += w[15] * cs + w[16] * sn;

    const float cc   = 1.0f / (1.0f + __expf(-z));
    const float term = diff[i] * cc;

    int p = parent[i];
    if (p < 0) p = N;
    g_nodes[i] = pack_node(p, term);
    if (i == 0) g_nodes[N] = pack_node(N, 0.0f);
}

__global__ __launch_bounds__(256)
void resolve_kernel(int N)
{
    const int i = blockIdx.x * blockDim.x + threadIdx.x;
    if (i >= N) return;

    ull cur = __ldcg(&g_nodes[i]);
    int   p = (int)(unsigned int)cur;
    float t = __uint_as_float((unsigned int)(cur >> 32));

    while (p != N) {
        const ull m = __ldcg(&g_nodes[p]);
        const int pp = (int)(unsigned int)m;
        t += __uint_as_float((unsigned int)(m >> 32));
        p = pp;
        __stcg(&g_nodes[i], pack_node(p, t));
    }
    g_val[i] = t;
}

__global__ __launch_bounds__(256)
void gather_kernel(const int* __restrict__ pn, float* __restrict__ out, int M)
{
    const int j = blockIdx.x * blockDim.x + threadIdx.x;
    const int i4 = j * 4;
    if (i4 + 3 < M) {
        const int4 p = __ldcs((const int4*)pn + j);
        float4 o;
        o.x = __ldg(&g_val[p.x]);
        o.y = __ldg(&g_val[p.y]);
        o.z = __ldg(&g_val[p.z]);
        o.w = __ldg(&g_val[p.w]);
        __stcs((float4*)out + j, o);
    } else {
        for (int k = i4; k < M; k++)
            out[k] = __ldg(&g_val[__ldcs(pn + k)]);
    }
}

extern "C" void kernel_launch(void* const* d_in, const int* in_sizes, int n_in,
                              void* d_out, int out_size)
{
    const float* diff   = (const float*)d_in[0];
    const float* attr   = (const float*)d_in[1];
    const float* weight = (const float*)d_in[2];
    const float* bias   = (const float*)d_in[3];
    const int*   parent = (const int*)d_in[4];
    const int*   pn     = (const int*)d_in[5];
    float*       out    = (float*)d_out;

    const int N = in_sizes[0];
    const int M = out_size;

    const int nb = (N + 255) / 256;
    phase1_kernel<<<nb, 256>>>(diff, attr, weight, bias, parent, N);
    resolve_kernel<<<nb, 256>>>(N);

    const int gthreads = (M + 3) / 4;
    const int gb = (gthreads + 255) / 256;
    gather_kernel<<<gb, 256>>>(pn, out, M);
}

// round 2
// speedup vs baseline: 1.0253x; 1.0253x over previous
#include <cuda_runtime.h>
#include <cstdint>

typedef unsigned long long ull;

#define MAXN (1 << 21)
#define NOT_READY 0xFFFFFFFFu   // p-field sentinel: entry not yet published (real p ∈ [0, N])

// g_nodes[i] packs {p : lo 32 bits, term/partial-sum : hi 32 bits} in one 8B word.
// After the fused kernel completes, g_nodes[i] = (N, full path sum) for all i.
__device__ ull g_nodes[MAXN + 1];

__device__ __forceinline__ ull pack_node(unsigned p, float t) {
    return ((ull)__float_as_uint(t) << 32) | (ull)p;
}
__device__ __forceinline__ ull ld_relaxed(const ull* a) {
    ull v;
    asm volatile("ld.relaxed.gpu.b64 %0, [%1];" : "=l"(v) : "l"(a) : "memory");
    return v;
}
__device__ __forceinline__ void st_relaxed(ull* a, ull v) {
    asm volatile("st.relaxed.gpu.b64 [%0], %1;" :: "l"(a), "l"(v) : "memory");
}

// ---------------------------------------------------------------------------
// Phase 0: mark every node NOT_READY; write the sentinel node N as final (N, 0).
// Required each replay since g_nodes persists across graph replays.
// ---------------------------------------------------------------------------
__global__ __launch_bounds__(256)
void init_kernel(int N)
{
    const int i = blockIdx.x * blockDim.x + threadIdx.x;
    if (i <= N)
        g_nodes[i] = (i == N) ? pack_node((unsigned)N, 0.0f)
                              : pack_node(NOT_READY, 0.0f);
}

// ---------------------------------------------------------------------------
// Phase 1 (fused): feature transform + linear + sigmoid -> term, publish
// (parent, term), then concurrently path-compress to root. Chase latency is
// hidden under the DRAM streaming of the attribute reads. parent[i] < i
// strictly => producer blocks have lower bids and are scheduled no later than
// consumers, so the readiness spin always terminates.
// ---------------------------------------------------------------------------
__global__ __launch_bounds__(256)
void fused_kernel(const float* __restrict__ diff,
                  const float* __restrict__ attr,
                  const float* __restrict__ weight,
                  const float* __restrict__ bias,
                  const int*   __restrict__ parent,
                  int N)
{
    __shared__ float s_attr[256 * 15];
    const int base = blockIdx.x * 256;
    const int tid  = threadIdx.x;

    if (base + 256 <= N) {
        const float4* src = (const float4*)(attr + (size_t)base * 15);
        float4* dst = (float4*)s_attr;
        // 256*15 floats = 960 float4s per block (read-once -> streaming hint)
        dst[tid]       = __ldcs(src + tid);
        dst[tid + 256] = __ldcs(src + tid + 256);
        dst[tid + 512] = __ldcs(src + tid + 512);
        if (tid < 192) dst[tid + 768] = __ldcs(src + tid + 768);
    } else {
        const int rem = (N - base) * 15;
        for (int k = tid; k < rem; k += 256)
            s_attr[k] = __ldcs(attr + (size_t)base * 15 + k);
    }
    __syncthreads();

    const int i = base + tid;
    if (i >= N) return;

    const float* f = s_attr + tid * 15;

    float w[17];
    #pragma unroll
    for (int k = 0; k < 17; k++) w[k] = __ldg(weight + k);

    float z = __ldg(bias);
    z += w[0] * f[0] + w[1] * f[1] + w[2] * f[2] + w[3] * f[3] + w[4] * f[4];
    #pragma unroll
    for (int j = 6; j < 15; j++)
        z += w[j - 1] * __logf(fabsf(f[j]) + 1e-10f);
    z += w[14] * (sqrtf(f[7]) / (sqrtf(f[6]) + 1e-10f));
    float sn, cs;
    __sincosf(f[5], &sn, &cs);
    z += w[15] * cs + w[16] * sn;

    const float cc   = 1.0f / (1.0f + __expf(-z));
    float t = __ldcs(diff + i) * cc;

    int pi = __ldcs(parent + i);
    unsigned p = (pi < 0) ? (unsigned)N : (unsigned)pi;

    // Publish initial state immediately so descendants can make progress.
    st_relaxed(&g_nodes[i], pack_node(p, t));

    // Concurrent path compression with readiness spin.
    while (p != (unsigned)N) {
        const ull m = ld_relaxed(&g_nodes[p]);
        const unsigned mp = (unsigned)m;
        if (mp == NOT_READY) { __nanosleep(40); continue; }
        t += __uint_as_float((unsigned)(m >> 32));
        p = mp;
        st_relaxed(&g_nodes[i], pack_node(p, t));  // publish compressed state
    }
}

// ---------------------------------------------------------------------------
// Phase 2: pixel gather. out[j] = hi32(g_nodes[pn[j]]). Streaming hints keep
// the 128MB pixel traffic from evicting the 16MB g_nodes array from L2.
// 8 pixels/thread for deep MLP on the random L2-bound loads.
// ---------------------------------------------------------------------------
__global__ __launch_bounds__(256)
void gather_kernel(const int* __restrict__ pn, float* __restrict__ out, int M)
{
    const int j  = blockIdx.x * blockDim.x + threadIdx.x;
    const int i8 = j * 8;
    if (i8 + 7 < M) {
        const int4 pa = __ldcs((const int4*)pn + 2 * j);
        const int4 pb = __ldcs((const int4*)pn + 2 * j + 1);
        float4 oa, ob;
        oa.x = __uint_as_float((unsigned)(__ldg(&g_nodes[pa.x]) >> 32));
        oa.y = __uint_as_float((unsigned)(__ldg(&g_nodes[pa.y]) >> 32));
        oa.z = __uint_as_float((unsigned)(__ldg(&g_nodes[pa.z]) >> 32));
        oa.w = __uint_as_float((unsigned)(__ldg(&g_nodes[pa.w]) >> 32));
        ob.x = __uint_as_float((unsigned)(__ldg(&g_nodes[pb.x]) >> 32));
        ob.y = __uint_as_float((unsigned)(__ldg(&g_nodes[pb.y]) >> 32));
        ob.z = __uint_as_float((unsigned)(__ldg(&g_nodes[pb.z]) >> 32));
        ob.w = __uint_as_float((unsigned)(__ldg(&g_nodes[pb.w]) >> 32));
        __stcs((float4*)out + 2 * j, oa);
        __stcs((float4*)out + 2 * j + 1, ob);
    } else {
        for (int k = i8; k < M; k++)
            out[k] = __uint_as_float((unsigned)(__ldg(&g_nodes[__ldcs(pn + k)]) >> 32));
    }
}

extern "C" void kernel_launch(void* const* d_in, const int* in_sizes, int n_in,
                              void* d_out, int out_size)
{
    const float* diff   = (const float*)d_in[0];
    const float* attr   = (const float*)d_in[1];
    const float* weight = (const float*)d_in[2];
    const float* bias   = (const float*)d_in[3];
    const int*   parent = (const int*)d_in[4];
    const int*   pn     = (const int*)d_in[5];
    float*       out    = (float*)d_out;

    const int N = in_sizes[0];
    const int M = out_size;

    init_kernel<<<(N + 1 + 255) / 256, 256>>>(N);
    fused_kernel<<<(N + 255) / 256, 256>>>(diff, attr, weight, bias, parent, N);

    const int gthreads = (M + 7) / 8;
    gather_kernel<<<(gthreads + 255) / 256, 256>>>(pn, out, M);
}

// round 3
// speedup vs baseline: 1.0564x; 1.0303x over previous
#include <cuda_runtime.h>
#include <cstdint>

typedef unsigned long long ull;

#define MAXN (1 << 21)

// g_nodes[i] packs {p : lo 32, partial-sum : hi 32}. One 8B word => each chase
// hop is a single L2 access. After a node is final: p == N, hi = full path sum.
__device__ ull   g_nodes[MAXN];
__device__ float g_val[MAXN];

__device__ __forceinline__ ull pack_node(unsigned p, float t) {
    return ((ull)__float_as_uint(t) << 32) | (ull)p;
}
__device__ __forceinline__ ull ld_cg(const ull* a) {
    ull v;
    asm volatile("ld.relaxed.gpu.b64 %0, [%1];" : "=l"(v) : "l"(a) : "memory");
    return v;
}
__device__ __forceinline__ void st_cg(ull* a, ull v) {
    asm volatile("st.relaxed.gpu.b64 [%0], %1;" :: "l"(a), "l"(v) : "memory");
}

// ---------------------------------------------------------------------------
// Phase 1: feature transform + linear + sigmoid -> term; publish (parent,term)
// for EVERY node. Kernel boundary then acts as the readiness barrier -> no
// init kernel, no sentinel, no spinning.
// ---------------------------------------------------------------------------
__global__ __launch_bounds__(256)
void phase1_kernel(const float* __restrict__ diff,
                   const float* __restrict__ attr,
                   const float* __restrict__ weight,
                   const float* __restrict__ bias,
                   const int*   __restrict__ parent,
                   int N)
{
    __shared__ float s_attr[256 * 15];
    const int base = blockIdx.x * 256;
    const int tid  = threadIdx.x;

    if (base + 256 <= N) {
        const float4* src = (const float4*)(attr + (size_t)base * 15);
        float4* dst = (float4*)s_attr;
        dst[tid]       = __ldcs(src + tid);
        dst[tid + 256] = __ldcs(src + tid + 256);
        dst[tid + 512] = __ldcs(src + tid + 512);
        if (tid < 192) dst[tid + 768] = __ldcs(src + tid + 768);
    } else {
        const int rem = (N - base) * 15;
        for (int k = tid; k < rem; k += 256)
            s_attr[k] = __ldcs(attr + (size_t)base * 15 + k);
    }
    __syncthreads();

    const int i = base + tid;
    if (i >= N) return;

    const float* f = s_attr + tid * 15;

    float w[17];
    #pragma unroll
    for (int k = 0; k < 17; k++) w[k] = __ldg(weight + k);

    float z = __ldg(bias);
    z += w[0] * f[0] + w[1] * f[1] + w[2] * f[2] + w[3] * f[3] + w[4] * f[4];
    #pragma unroll
    for (int j = 6; j < 15; j++)
        z += w[j - 1] * __logf(fabsf(f[j]) + 1e-10f);
    z += w[14] * (sqrtf(f[7]) / (sqrtf(f[6]) + 1e-10f));
    float sn, cs;
    __sincosf(f[5], &sn, &cs);
    z += w[15] * cs + w[16] * sn;

    const float cc = 1.0f / (1.0f + __expf(-z));
    const float t  = __ldcs(diff + i) * cc;

    const int pi = __ldcs(parent + i);
    const unsigned p = (pi < 0) ? (unsigned)N : (unsigned)pi;
    g_nodes[i] = pack_node(p, t);
}

// ---------------------------------------------------------------------------
// Resolve one slab [start, end). Invariant: every node < start is already
// final (p == N). parent[i] < i, so a chase exits the slab in ~1 expected
// in-slab hop (geometric slabs), then one read of a final ancestor ends it.
// In-slab concurrent compression races are benign: every published 8B state
// is a valid (ancestor, partial-sum) pair, and p strictly decreases.
// ---------------------------------------------------------------------------
__global__ __launch_bounds__(256)
void resolve_slab_kernel(int start, int end, int N)
{
    const int i = start + blockIdx.x * blockDim.x + threadIdx.x;
    if (i >= end) return;
    const unsigned Nu = (unsigned)N;

    ull cur = ld_cg(&g_nodes[i]);
    unsigned p = (unsigned)cur;
    float    t = __uint_as_float((unsigned)(cur >> 32));

    while (p != Nu) {
        const ull m = ld_cg(&g_nodes[p]);
        t += __uint_as_float((unsigned)(m >> 32));
        p = (unsigned)m;
        st_cg(&g_nodes[i], pack_node(p, t));   // publish (final state included)
    }
    g_val[i] = t;
}

// ---------------------------------------------------------------------------
// Gather: out[j] = g_val[pn[j]]. Streaming hints on the 128MB pixel traffic
// keep the 8MB g_val hot in L2; 8 pixels/thread for MLP on random loads.
// ---------------------------------------------------------------------------
__global__ __launch_bounds__(256)
void gather_kernel(const int* __restrict__ pn, float* __restrict__ out, int M)
{
    const int j  = blockIdx.x * blockDim.x + threadIdx.x;
    const int i8 = j * 8;
    if (i8 + 7 < M) {
        const int4 pa = __ldcs((const int4*)pn + 2 * j);
        const int4 pb = __ldcs((const int4*)pn + 2 * j + 1);
        float4 oa, ob;
        oa.x = __ldg(&g_val[pa.x]);
        oa.y = __ldg(&g_val[pa.y]);
        oa.z = __ldg(&g_val[pa.z]);
        oa.w = __ldg(&g_val[pa.w]);
        ob.x = __ldg(&g_val[pb.x]);
        ob.y = __ldg(&g_val[pb.y]);
        ob.z = __ldg(&g_val[pb.z]);
        ob.w = __ldg(&g_val[pb.w]);
        __stcs((float4*)out + 2 * j, oa);
        __stcs((float4*)out + 2 * j + 1, ob);
    } else {
        for (int k = i8; k < M; k++)
            out[k] = __ldg(&g_val[__ldcs(pn + k)]);
    }
}

extern "C" void kernel_launch(void* const* d_in, const int* in_sizes, int n_in,
                              void* d_out, int out_size)
{
    const float* diff   = (const float*)d_in[0];
    const float* attr   = (const float*)d_in[1];
    const float* weight = (const float*)d_in[2];
    const float* bias   = (const float*)d_in[3];
    const int*   parent = (const int*)d_in[4];
    const int*   pn     = (const int*)d_in[5];
    float*       out    = (float*)d_out;

    const int N = in_sizes[0];
    const int M = out_size;

    phase1_kernel<<<(N + 255) / 256, 256>>>(diff, attr, weight, bias, parent, N);

    // Geometric slabs: [0,8K), [8K,32K), [32K,128K), [128K,512K), [512K,N).
    int bounds[6];
    bounds[0] = 0;
    int b = N >> 8;               // 8K when N = 2^21
    for (int k = 1; k <= 4; k++) { bounds[k] = (b < N) ? b : N; b <<= 2; }
    bounds[5] = N;
    for (int k = 0; k < 5; k++) {
        const int s = bounds[k], e = bounds[k + 1];
        if (e > s)
            resolve_slab_kernel<<<(e - s + 255) / 256, 256>>>(s, e, N);
    }

    const int gthreads = (M + 7) / 8;
    gather_kernel<<<(gthreads + 255) / 256, 256>>>(pn, out, M);
}